// round 4
// baseline (speedup 1.0000x reference)
#include <cuda_runtime.h>
#include <cuda_bf16.h>
#include <stdint.h>

// Rejection sampler for speculative decoding — 3-kernel pipeline.
// Output float32 [B*(K+1) + 4*B]:
//  out[B,K+1], num_accepted[B], accepted_counts[B], recovered_counts[B], bonus_counts[B]

#define NT      256
#define MAXB    512      // max sequences
#define MAXC    512      // max 256-elem chunks (V <= 131072)
#define MAXK    16       // max spec len supported in K1 local arrays
#define SLICES  8        // streaming blocks per rejected sequence

// ---- device scratch (allocation-free) ----
__device__ int   g_nrej;
__device__ int   g_rej_b[MAXB];
__device__ int   g_rej_row[MAXB];
__device__ int   g_rej_numacc[MAXB];
__device__ float g_chunkA[MAXB * MAXC];
__device__ float g_chunkT[MAXB * MAXC];

// ================= K1: accept phase + compaction (1 block) =================
__global__ __launch_bounds__(NT) void k1_setup(
    const int* __restrict__ dtoks,
    const int* __restrict__ ndraft,
    const float* __restrict__ dp,
    const float* __restrict__ tp,
    const int* __restrict__ bonus,
    const float* __restrict__ us,
    float* __restrict__ out,
    int B, int K, long long V)
{
    const int t = threadIdx.x;
    const int w = t >> 5;
    const int lane = t & 31;

    __shared__ int sh_wsum[8];
    __shared__ int sh_cnt;
    if (t == 0) sh_cnt = 0;

    // inclusive scan of ndraft across the block -> start offsets
    int own = (t < B) ? ndraft[t] : 0;
    int inc = own;
    #pragma unroll
    for (int d = 1; d < 32; d <<= 1) {
        int y = __shfl_up_sync(0xffffffffu, inc, d);
        if (lane >= d) inc += y;
    }
    if (lane == 31) sh_wsum[w] = inc;
    __syncthreads();
    int woff = 0;
    #pragma unroll
    for (int i = 0; i < 8; i++) woff += (i < w) ? sh_wsum[i] : 0;
    const int start = woff + inc - own;   // exclusive prefix
    const int nb = own;

    if (t < B) {
        // load draft tokens (independent loads)
        int toks[MAXK];
        #pragma unroll 8
        for (int k = 0; k < K; k++)
            toks[k] = (k < nb) ? dtoks[start + k] : 0;
        // probs + uniforms (independent)
        int acc[MAXK];
        #pragma unroll 8
        for (int k = 0; k < K; k++) {
            acc[k] = 0;
            if (k < nb) {
                int idx = start + k;
                float pd = fmaxf(dp[(size_t)idx * V + toks[k]], 1e-10f);
                float pt = tp[(size_t)idx * V + toks[k]];
                float ap = fminf(1.0f, pt / pd);
                acc[k] = (us[idx] < ap) ? 1 : 0;
            }
        }
        int numacc = 0;
        while (numacc < nb && acc[numacc]) numacc++;
        const bool allacc = (numacc == nb);

        // output row
        for (int k = 0; k <= K; k++) {
            if (k < numacc)            out[t * (K + 1) + k] = (float)toks[k];
            else if (k == numacc) {
                if (allacc)            out[t * (K + 1) + k] = (float)bonus[t];
                // else: K3 fills recovered token
            } else                     out[t * (K + 1) + k] = -1.0f;
        }
        int base = B * (K + 1);
        out[base + t]         = (float)(numacc + 1);
        out[base + B + t]     = (float)numacc;
        out[base + 2 * B + t] = allacc ? 0.0f : 1.0f;
        out[base + 3 * B + t] = allacc ? 1.0f : 0.0f;

        if (!allacc) {
            int pos = atomicAdd(&sh_cnt, 1);
            g_rej_b[pos]      = t;
            g_rej_row[pos]    = start + numacc;
            g_rej_numacc[pos] = numacc;
        }
    }
    __syncthreads();
    if (t == 0) g_nrej = sh_cnt;
}

// ================= K2: streaming chunk sums (B*SLICES blocks) =================
__global__ __launch_bounds__(NT) void k2_stream(
    const float* __restrict__ dp,
    const float* __restrict__ tp,
    long long V)
{
    const int r = blockIdx.x / SLICES;
    const int s = blockIdx.x % SLICES;
    if (r >= g_nrej) return;

    const int row = g_rej_row[r];
    const float* __restrict__ trow = tp + (size_t)row * V;
    const float* __restrict__ drow = dp + (size_t)row * V;

    const int nchunks = (int)((V + 255) / 256);
    const int cps = (nchunks + SLICES - 1) / SLICES;
    const int c0 = s * cps;
    const int c1 = min(c0 + cps, nchunks);

    const int w = threadIdx.x >> 5;
    const int lane = threadIdx.x & 31;

    for (int c = c0 + w; c < c1; c += 8) {
        long long base = (long long)c * 256;
        float sa = 0.f, st = 0.f;
        #pragma unroll
        for (int l = 0; l < 8; l++) {
            long long j = base + l * 32 + lane;
            if (j < V) {
                float tv = trow[j];
                float dv = drow[j];
                st += tv;
                sa += fmaxf(tv - dv, 0.f);
            }
        }
        #pragma unroll
        for (int off = 16; off; off >>= 1) {
            sa += __shfl_down_sync(0xffffffffu, sa, off);
            st += __shfl_down_sync(0xffffffffu, st, off);
        }
        if (lane == 0) {
            g_chunkA[r * MAXC + c] = sa;
            g_chunkT[r * MAXC + c] = st;
        }
    }
}

// ================= K3: scan + select recovered token (B blocks) =================
__global__ __launch_bounds__(NT) void k3_select(
    const float* __restrict__ dp,
    const float* __restrict__ tp,
    const float* __restrict__ ru,
    float* __restrict__ out,
    int K, long long V)
{
    const int r = blockIdx.x;
    if (r >= g_nrej) return;

    const int t = threadIdx.x;
    const int lane = t & 31;
    const int b = g_rej_b[r];
    const int row = g_rej_row[r];
    const int numacc = g_rej_numacc[r];
    const int nchunks = (int)((V + 255) / 256);

    __shared__ float sA[MAXC];
    __shared__ float sT[MAXC];
    __shared__ float sh_thr, sh_coff;
    __shared__ int   sh_cstar, sh_modeT;

    for (int i = t; i < nchunks; i += NT) {
        sA[i] = g_chunkA[r * MAXC + i];
        sT[i] = g_chunkT[r * MAXC + i];
    }
    __syncthreads();

    if (t == 0) {
        float sTot = 0.f;
        for (int c = 0; c < nchunks; c++) sTot += sA[c];
        int modeT = !(sTot > 1e-10f);
        float u = ru[b];
        float thr = modeT ? u : u * sTot;
        const float* cs = modeT ? sT : sA;
        float pref = 0.f, coff = 0.f;
        int cstar = nchunks;
        for (int c = 0; c < nchunks; c++) {
            float np = pref + cs[c];
            if (np >= thr) { cstar = c; coff = pref; break; }
            pref = np;
        }
        sh_thr = thr; sh_coff = coff; sh_cstar = cstar; sh_modeT = modeT;
    }
    __syncthreads();

    if (t < 32) {
        const float* __restrict__ trow = tp + (size_t)row * V;
        const float* __restrict__ drow = dp + (size_t)row * V;
        int cstar = sh_cstar;
        int recovered;
        if (cstar >= nchunks) {
            recovered = (int)V - 1;
        } else {
            float thr = sh_thr;
            float off = sh_coff;
            bool modeT = (sh_modeT != 0);
            long long base = (long long)cstar * 256;
            float vals[8];
            float lsum = 0.f;
            #pragma unroll
            for (int l = 0; l < 8; l++) {
                long long j = base + lane * 8 + l;
                float a = 0.f;
                if (j < V) {
                    float tv = trow[j];
                    a = modeT ? tv : fmaxf(tv - drow[j], 0.f);
                }
                vals[l] = a;
                lsum += a;
            }
            float incv = lsum;
            #pragma unroll
            for (int d = 1; d < 32; d <<= 1) {
                float y = __shfl_up_sync(0xffffffffu, incv, d);
                if (lane >= d) incv += y;
            }
            float p = off + (incv - lsum);
            int cnt = 0;
            #pragma unroll
            for (int l = 0; l < 8; l++) {
                p += vals[l];
                long long j = base + lane * 8 + l;
                if (p < thr && j < V) cnt++;
            }
            #pragma unroll
            for (int o = 16; o; o >>= 1)
                cnt += __shfl_down_sync(0xffffffffu, cnt, o);
            recovered = (int)base + cnt;
            if (recovered > (int)V - 1) recovered = (int)V - 1;
        }
        if (lane == 0)
            out[b * (K + 1) + numacc] = (float)recovered;
    }
}

extern "C" void kernel_launch(void* const* d_in, const int* in_sizes, int n_in,
                              void* d_out, int out_size)
{
    const int*   dtoks  = (const int*)  d_in[0];
    const int*   ndraft = (const int*)  d_in[1];
    const float* dp     = (const float*)d_in[2];
    const float* tp     = (const float*)d_in[3];
    const int*   bonus  = (const int*)  d_in[4];
    const float* us     = (const float*)d_in[5];
    const float* ru     = (const float*)d_in[6];

    int T = in_sizes[0];
    int B = in_sizes[1];
    long long V = (long long)in_sizes[2] / T;
    int K = out_size / B - 5;   // out layout: B*(K+1) + 4*B

    float* out = (float*)d_out;

    k1_setup <<<1, NT>>>(dtoks, ndraft, dp, tp, bonus, us, out, B, K, V);
    k2_stream<<<B * SLICES, NT>>>(dp, tp, V);
    k3_select<<<B, NT>>>(dp, tp, ru, out, K, V);
}

// round 7
// speedup vs baseline: 1.1525x; 1.1525x over previous
#include <cuda_runtime.h>
#include <cuda_bf16.h>
#include <stdint.h>

// Rejection sampler for speculative decoding — 3-kernel pipeline, all phases
// chip-wide parallel.
// Output float32 [B*(K+1) + 4*B]:
//  out[B,K+1], num_accepted[B], accepted_counts[B], recovered_counts[B], bonus_counts[B]

#define NT      256
#define MAXB    512      // max sequences
#define MAXC    512      // max 256-elem chunks (V <= 131072)
#define SLICES  8        // streaming blocks per rejected sequence

// ---- device scratch (allocation-free) ----
__device__ int   g_rej[MAXB];      // 1 if sequence rejected (needs resample)
__device__ int   g_row[MAXB];      // packed row of first rejected position
__device__ int   g_numacc[MAXB];   // accepted prefix length
__device__ float g_chunkA[MAXB * MAXC];
__device__ float g_chunkT[MAXB * MAXC];

// ================= K1: accept phase (B blocks, warp-0 per sequence) =========
__global__ __launch_bounds__(NT) void k1_setup(
    const int* __restrict__ dtoks,
    const int* __restrict__ ndraft,
    const float* __restrict__ dp,
    const float* __restrict__ tp,
    const int* __restrict__ bonus,
    const float* __restrict__ us,
    float* __restrict__ out,
    int B, int K, long long V)
{
    const int b = blockIdx.x;
    const int t = threadIdx.x;
    const int w = t >> 5;
    const int lane = t & 31;

    __shared__ int sh_red[8];
    __shared__ int sh_start;
    __shared__ int sh_numacc;
    __shared__ int sh_allacc;
    __shared__ int sh_dtok[32];

    // starts[b] = sum of ndraft[0..b-1], block reduce (ndraft L2-hot)
    {
        int v = (t < b) ? ndraft[t] : 0;
        #pragma unroll
        for (int off = 16; off; off >>= 1)
            v += __shfl_down_sync(0xffffffffu, v, off);
        if (lane == 0) sh_red[w] = v;
        __syncthreads();
        if (t == 0) {
            int s = 0;
            #pragma unroll
            for (int i = 0; i < 8; i++) s += sh_red[i];
            sh_start = s;
        }
        __syncthreads();
    }
    const int start = sh_start;
    const int nb = ndraft[b];

    // accept decisions: one lane per draft position
    if (t < 32) {
        int k = lane;
        int acc = 0;
        if (k < nb) {
            int idx = start + k;
            int tok = dtoks[idx];
            float pd = fmaxf(dp[(size_t)idx * V + tok], 1e-10f);
            float pt = tp[(size_t)idx * V + tok];
            float ap = fminf(1.0f, pt / pd);
            acc = (us[idx] < ap) ? 1 : 0;
            sh_dtok[k] = tok;
        }
        unsigned m = __ballot_sync(0xffffffffu, (k >= nb) || !acc);
        int numacc = __ffs(m) - 1;
        if (lane == 0) {
            sh_numacc = numacc;
            sh_allacc = (numacc == nb) ? 1 : 0;
        }
    }
    __syncthreads();
    const int numacc = sh_numacc;
    const bool allacc = (sh_allacc != 0);

    // light outputs
    if (t <= K) {
        bool is_final = (t == numacc);
        float v;
        if (t < numacc)      v = (float)sh_dtok[t];
        else if (is_final)   v = (float)bonus[b];   // valid only if allacc
        else                 v = -1.0f;
        if (!(is_final && !allacc))
            out[b * (K + 1) + t] = v;
    }
    if (t == 0) {
        int base = B * (K + 1);
        out[base + b]         = (float)(numacc + 1);
        out[base + B + b]     = (float)numacc;
        out[base + 2 * B + b] = allacc ? 0.0f : 1.0f;
        out[base + 3 * B + b] = allacc ? 1.0f : 0.0f;
        g_rej[b]    = allacc ? 0 : 1;
        g_row[b]    = start + numacc;
        g_numacc[b] = numacc;
    }
}

// ================= K2: streaming chunk sums (B*SLICES blocks) =================
__global__ __launch_bounds__(NT) void k2_stream(
    const float* __restrict__ dp,
    const float* __restrict__ tp,
    long long V)
{
    const int b = blockIdx.x / SLICES;
    const int s = blockIdx.x % SLICES;
    if (!g_rej[b]) return;

    const int row = g_row[b];
    const float* __restrict__ trow = tp + (size_t)row * V;
    const float* __restrict__ drow = dp + (size_t)row * V;

    const int nchunks = (int)((V + 255) / 256);
    const int cps = (nchunks + SLICES - 1) / SLICES;
    const int c0 = s * cps;
    const int c1 = min(c0 + cps, nchunks);

    const int w = threadIdx.x >> 5;
    const int lane = threadIdx.x & 31;

    for (int c = c0 + w; c < c1; c += 8) {
        long long base = (long long)c * 256;
        float sa = 0.f, st = 0.f;
        #pragma unroll
        for (int l = 0; l < 8; l++) {
            long long j = base + l * 32 + lane;
            if (j < V) {
                float tv = __ldcs(trow + j);   // read-once stream: evict-first
                float dv = __ldcs(drow + j);
                st += tv;
                sa += fmaxf(tv - dv, 0.f);
            }
        }
        #pragma unroll
        for (int off = 16; off; off >>= 1) {
            sa += __shfl_down_sync(0xffffffffu, sa, off);
            st += __shfl_down_sync(0xffffffffu, st, off);
        }
        if (lane == 0) {
            g_chunkA[b * MAXC + c] = sa;
            g_chunkT[b * MAXC + c] = st;
        }
    }
}

// ================= K3: scan + select recovered token (B blocks) =================
__global__ __launch_bounds__(NT) void k3_select(
    const float* __restrict__ dp,
    const float* __restrict__ tp,
    const float* __restrict__ ru,
    float* __restrict__ out,
    int K, long long V)
{
    const int b = blockIdx.x;
    if (!g_rej[b]) return;

    const int t = threadIdx.x;
    const int lane = t & 31;
    const int row = g_row[b];
    const int numacc = g_numacc[b];
    const int nchunks = (int)((V + 255) / 256);

    __shared__ float sA[MAXC];
    __shared__ float sT[MAXC];
    __shared__ float sh_thr, sh_coff;
    __shared__ int   sh_cstar, sh_modeT;

    for (int i = t; i < nchunks; i += NT) {
        sA[i] = g_chunkA[b * MAXC + i];
        sT[i] = g_chunkT[b * MAXC + i];
    }
    __syncthreads();

    if (t == 0) {
        float sTot = 0.f;
        for (int c = 0; c < nchunks; c++) sTot += sA[c];
        int modeT = !(sTot > 1e-10f);
        float u = ru[b];
        float thr = modeT ? u : u * sTot;
        const float* cs = modeT ? sT : sA;
        float pref = 0.f, coff = 0.f;
        int cstar = nchunks;
        for (int c = 0; c < nchunks; c++) {
            float np = pref + cs[c];
            if (np >= thr) { cstar = c; coff = pref; break; }
            pref = np;
        }
        sh_thr = thr; sh_coff = coff; sh_cstar = cstar; sh_modeT = modeT;
    }
    __syncthreads();

    if (t < 32) {
        const float* __restrict__ trow = tp + (size_t)row * V;
        const float* __restrict__ drow = dp + (size_t)row * V;
        int cstar = sh_cstar;
        int recovered;
        if (cstar >= nchunks) {
            recovered = (int)V - 1;
        } else {
            float thr = sh_thr;
            float off = sh_coff;
            bool modeT = (sh_modeT != 0);
            long long base = (long long)cstar * 256;
            float vals[8];
            float lsum = 0.f;
            #pragma unroll
            for (int l = 0; l < 8; l++) {
                long long j = base + lane * 8 + l;
                float a = 0.f;
                if (j < V) {
                    float tv = trow[j];
                    a = modeT ? tv : fmaxf(tv - drow[j], 0.f);
                }
                vals[l] = a;
                lsum += a;
            }
            float incv = lsum;
            #pragma unroll
            for (int d = 1; d < 32; d <<= 1) {
                float y = __shfl_up_sync(0xffffffffu, incv, d);
                if (lane >= d) incv += y;
            }
            float p = off + (incv - lsum);
            int cnt = 0;
            #pragma unroll
            for (int l = 0; l < 8; l++) {
                p += vals[l];
                long long j = base + lane * 8 + l;
                if (p < thr && j < V) cnt++;
            }
            #pragma unroll
            for (int o = 16; o; o >>= 1)
                cnt += __shfl_down_sync(0xffffffffu, cnt, o);
            recovered = (int)base + cnt;
            if (recovered > (int)V - 1) recovered = (int)V - 1;
        }
        if (lane == 0)
            out[b * (K + 1) + numacc] = (float)recovered;
    }
}

extern "C" void kernel_launch(void* const* d_in, const int* in_sizes, int n_in,
                              void* d_out, int out_size)
{
    const int*   dtoks  = (const int*)  d_in[0];
    const int*   ndraft = (const int*)  d_in[1];
    const float* dp     = (const float*)d_in[2];
    const float* tp     = (const float*)d_in[3];
    const int*   bonus  = (const int*)  d_in[4];
    const float* us     = (const float*)d_in[5];
    const float* ru     = (const float*)d_in[6];

    int T = in_sizes[0];
    int B = in_sizes[1];
    long long V = (long long)in_sizes[2] / T;
    int K = out_size / B - 5;   // out layout: B*(K+1) + 4*B

    float* out = (float*)d_out;

    k1_setup <<<B, NT>>>(dtoks, ndraft, dp, tp, bonus, us, out, B, K, V);
    k2_stream<<<B * SLICES, NT>>>(dp, tp, V);
    k3_select<<<B, NT>>>(dp, tp, ru, out, K, V);
}